// round 13
// baseline (speedup 1.0000x reference)
#include <cuda_runtime.h>
#include <cuda_bf16.h>

#define BIG 1e4f
#define IMH 1024
#define IMW 1024

constexpr int TY      = 32;               // output rows per warp
constexpr int NSEG    = 4;                // 1024/256: warp covers 256 floats
constexpr int NSTRIP  = IMH / TY;         // 32
constexpr int NTHREADS = 256;             // 8 warps / block
// warps = 24*32*4 = 3072 -> 384 blocks -> 20.8 warps/SM, ALL resident (3 blocks/SM)

// ---------------- cross fast path: 8 output columns per lane ----------------
// Halos come from neighbor lanes via SHFL; only lane 0/31 at segment edges load.
// EDGE=false: strip interior in y (rows y0-2..y0+TY+1 all in-bounds) -> no clamps.
template<bool EDGE>
__device__ __forceinline__ void run_warp8_cross(const float* __restrict__ src,
                                                float*       __restrict__ dst,
                                                int x0, int y0, int lane,
                                                bool segL, bool segR)
{
    float eA[10], eB[10];  // erosion rows q-1, q   (x0-1 .. x0+8)
    float dA[8],  dB[8];   // dilation rows q-2, q-1 (x0 .. x0+7)
#pragma unroll
    for (int k = 0; k < 10; k++) { eA[k] = BIG; eB[k] = BIG; }
#pragma unroll
    for (int k = 0; k < 8; k++)  { dA[k] = -BIG; dB[k] = -BIG; }

    const bool xlo = (x0 == 0);             // eroded pos x0-1 == -1 (lane0 of seg0)
    const bool xhi = (x0 == IMW - 8);       // eroded pos x0+8 == IMW (lane31 of seg3)
    const bool ldL = (lane == 0)  && !segL; // this lane loads the left  halo float2
    const bool ldR = (lane == 31) && !segR; // this lane loads the right halo float2
    const float* __restrict__ pbase = src + x0;

#pragma unroll 3
    for (int q = y0 - 2; q <= y0 + TY + 1; q++) {
        // ---- row pointer (EDGE clamps) ----
        const float* p;
        if (EDGE) {
            int qc = q < 0 ? 0 : (q >= IMH ? IMH - 1 : q);
            p = pbase + (size_t)qc * IMW;
        } else {
            p = pbase + (size_t)q * IMW;
        }

        // ---- 2 vector loads (all lanes) + predicated edge-lane halo loads ----
        float4 v0 = *reinterpret_cast<const float4*>(p);
        float4 v1 = *reinterpret_cast<const float4*>(p + 4);
        float2 lv2 = make_float2(BIG, BIG);
        float2 rv2 = make_float2(BIG, BIG);
        if (ldL) lv2 = *reinterpret_cast<const float2*>(p - 2);
        if (ldR) rv2 = *reinterpret_cast<const float2*>(p + 8);

        // ---- halos via shuffle (uniform control flow) ----
        float lx = __shfl_up_sync(0xffffffffu, v1.z, 1);   // lane l-1 col +6
        float ly = __shfl_up_sync(0xffffffffu, v1.w, 1);   // lane l-1 col +7
        float rx = __shfl_down_sync(0xffffffffu, v0.x, 1); // lane l+1 col +0
        float ry = __shfl_down_sync(0xffffffffu, v0.y, 1); // lane l+1 col +1
        if (lane == 0)  { lx = lv2.x; ly = lv2.y; }        // BIG if seg edge
        if (lane == 31) { rx = rv2.x; ry = rv2.y; }

        float w[12];
        w[0]=lx;   w[1]=ly;
        w[2]=v0.x; w[3]=v0.y; w[4]=v0.z; w[5]=v0.w;
        w[6]=v1.x; w[7]=v1.y; w[8]=v1.z; w[9]=v1.w;
        w[10]=rx;  w[11]=ry;
        if (EDGE && (q < 0 || q >= IMH)) {
#pragma unroll
            for (int k = 0; k < 12; k++) w[k] = BIG;
        }

        // ---- erosion contributions of input row q (10-wide) ----
        float eC[10];
#pragma unroll
        for (int k = 0; k < 10; k++) {
            float h = fminf(fminf(w[k], w[k + 1]), w[k + 2]);
            eC[k] = w[k + 1];               // mask row 0: center only
            eB[k] = fminf(eB[k], h);        // mask row 1: full
            eA[k] = fminf(eA[k], w[k + 1]); // mask row 2: center only
        }

        // ---- eA complete: eroded row ry = q-1; -BIG padding ----
        if (EDGE) {
            int ryy = q - 1;
            if (ryy < 0 || ryy >= IMH) {
#pragma unroll
                for (int k = 0; k < 10; k++) eA[k] = -BIG;
            } else {
                if (xlo) eA[0] = -BIG;
                if (xhi) eA[9] = -BIG;
            }
        } else {
            if (xlo) eA[0] = -BIG;
            if (xhi) eA[9] = -BIG;
        }

        // ---- dilation contributions of eroded row (8-wide) ----
        float dC[8];
#pragma unroll
        for (int k = 0; k < 8; k++) {
            float g = fmaxf(fmaxf(eA[k], eA[k + 1]), eA[k + 2]);
            dC[k] = eA[k + 1];
            dB[k] = fmaxf(dB[k], g);
            dA[k] = fmaxf(dA[k], eA[k + 1]);
        }

        // ---- dA complete: output row sy = q-2 ----
        if (q >= y0 + 2) {
            int sy = q - 2;
            float* o = dst + (size_t)sy * IMW + x0;
            *reinterpret_cast<float4*>(o)     = make_float4(dA[0], dA[1], dA[2], dA[3]);
            *reinterpret_cast<float4*>(o + 4) = make_float4(dA[4], dA[5], dA[6], dA[7]);
        }

        // ---- rotate pipelines (unroll 3 == period -> renamed away) ----
#pragma unroll
        for (int k = 0; k < 10; k++) { eA[k] = eB[k]; eB[k] = eC[k]; }
#pragma unroll
        for (int k = 0; k < 8; k++)  { dA[k] = dB[k]; dB[k] = dC[k]; }
    }
}

// ---------------- generic-mask fallback: 4 columns per call ----------------
__device__ void run_warp4_generic(const float* __restrict__ src,
                                  float*       __restrict__ dst,
                                  const int* km, int x0, int y0)
{
    float eA[6], eB[6];
    float dA[4], dB[4];
#pragma unroll
    for (int k = 0; k < 6; k++) { eA[k] = BIG; eB[k] = BIG; }
#pragma unroll
    for (int k = 0; k < 4; k++) { dA[k] = -BIG; dB[k] = -BIG; }

    const bool xlo = (x0 == 0);
    const bool xhi = (x0 == IMW - 4);
    const int  offL = (x0 >= 2)       ? -2 : 0;
    const int  offR = (x0 <= IMW - 8) ?  4 : 0;
    const bool padL = (x0 < 2);
    const bool padR = (x0 > IMW - 8);
    const float* __restrict__ pbase = src + x0;

    for (int q = y0 - 2; q <= y0 + TY + 1; q++) {
        int qc = q < 0 ? 0 : (q >= IMH ? IMH - 1 : q);
        const float* p = pbase + (size_t)qc * IMW;
        float4 v  = *reinterpret_cast<const float4*>(p);
        float2 lv = *reinterpret_cast<const float2*>(p + offL);
        float2 rv = *reinterpret_cast<const float2*>(p + offR);
        if (padL) { lv.x = BIG; lv.y = BIG; }
        if (padR) { rv.x = BIG; rv.y = BIG; }
        float w[8];
        w[0]=lv.x; w[1]=lv.y; w[2]=v.x; w[3]=v.y; w[4]=v.z; w[5]=v.w; w[6]=rv.x; w[7]=rv.y;
        if (q < 0 || q >= IMH) {
#pragma unroll
            for (int k = 0; k < 8; k++) w[k] = BIG;
        }

        float c0[6], c1[6], c2[6];
#pragma unroll
        for (int k = 0; k < 6; k++) { c0[k] = BIG; c1[k] = BIG; c2[k] = BIG; }
#pragma unroll
        for (int j = 0; j < 3; j++) {
            if (km[0*3 + j]) {
#pragma unroll
                for (int k = 0; k < 6; k++) c0[k] = fminf(c0[k], w[k + j]);
            }
            if (km[1*3 + j]) {
#pragma unroll
                for (int k = 0; k < 6; k++) c1[k] = fminf(c1[k], w[k + j]);
            }
            if (km[2*3 + j]) {
#pragma unroll
                for (int k = 0; k < 6; k++) c2[k] = fminf(c2[k], w[k + j]);
            }
        }
        float eC[6];
#pragma unroll
        for (int k = 0; k < 6; k++) {
            eC[k] = c0[k];
            eB[k] = fminf(eB[k], c1[k]);
            eA[k] = fminf(eA[k], c2[k]);
        }

        int ry = q - 1;
        if (ry < 0 || ry >= IMH) {
#pragma unroll
            for (int k = 0; k < 6; k++) eA[k] = -BIG;
        } else {
            if (xlo) eA[0] = -BIG;
            if (xhi) eA[5] = -BIG;
        }

        float g0[4], g1[4], g2[4];
#pragma unroll
        for (int k = 0; k < 4; k++) { g0[k] = -BIG; g1[k] = -BIG; g2[k] = -BIG; }
#pragma unroll
        for (int j = 0; j < 3; j++) {
            if (km[0*3 + j]) {
#pragma unroll
                for (int k = 0; k < 4; k++) g0[k] = fmaxf(g0[k], eA[k + j]);
            }
            if (km[1*3 + j]) {
#pragma unroll
                for (int k = 0; k < 4; k++) g1[k] = fmaxf(g1[k], eA[k + j]);
            }
            if (km[2*3 + j]) {
#pragma unroll
                for (int k = 0; k < 4; k++) g2[k] = fmaxf(g2[k], eA[k + j]);
            }
        }
        float dC[4];
#pragma unroll
        for (int k = 0; k < 4; k++) {
            dC[k] = g0[k];
            dB[k] = fmaxf(dB[k], g1[k]);
            dA[k] = fmaxf(dA[k], g2[k]);
        }

        if (q >= y0 + 2) {
            int sy = q - 2;
            *reinterpret_cast<float4*>(dst + (size_t)sy * IMW + x0) =
                make_float4(dA[0], dA[1], dA[2], dA[3]);
        }

#pragma unroll
        for (int k = 0; k < 6; k++) { eA[k] = eB[k]; eB[k] = eC[k]; }
#pragma unroll
        for (int k = 0; k < 4; k++) { dA[k] = dB[k]; dB[k] = dC[k]; }
    }
}

__global__ __launch_bounds__(NTHREADS, 3)
void opening_kernel(const float* __restrict__ img,
                    const int*   __restrict__ ker,
                    float*       __restrict__ out)
{
    int km[9];
#pragma unroll
    for (int i = 0; i < 9; i++) km[i] = ker[i];
    const bool cross = (km[0] == 0) && (km[1] == 1) && (km[2] == 0) &&
                       (km[3] == 1) && (km[4] == 1) && (km[5] == 1) &&
                       (km[6] == 0) && (km[7] == 1) && (km[8] == 0);

    const int gw   = blockIdx.x * (NTHREADS / 32) + (threadIdx.x >> 5);
    const int lane = threadIdx.x & 31;
    const int xseg   = gw & (NSEG - 1);       // 2 bits
    const int t      = gw >> 2;
    const int ystrip = t & (NSTRIP - 1);      // 5 bits
    const int bc     = t >> 5;

    const int x0 = xseg * 256 + lane * 8;
    const int y0 = ystrip * TY;
    const bool segL = (xseg == 0);
    const bool segR = (xseg == NSEG - 1);

    const float* src = img + (size_t)bc * (IMH * IMW);
    float*       dst = out + (size_t)bc * (IMH * IMW);

    if (cross) {
        if (y0 >= 2 && y0 + TY + 1 < IMH)     // rows y0-2 .. y0+TY+1 all in-bounds
            run_warp8_cross<false>(src, dst, x0, y0, lane, segL, segR);
        else
            run_warp8_cross<true >(src, dst, x0, y0, lane, segL, segR);
    } else {
        run_warp4_generic(src, dst, km, x0,     y0);
        run_warp4_generic(src, dst, km, x0 + 4, y0);
    }
}

extern "C" void kernel_launch(void* const* d_in, const int* in_sizes, int n_in,
                              void* d_out, int out_size)
{
    const float* img = (const float*)d_in[0];   // [8,3,1024,1024] fp32
    const int*   ker = (const int*)d_in[1];     // [3,3] int32 mask
    float*       out = (float*)d_out;

    const int BC = in_sizes[0] / (IMH * IMW);   // 24
    const int warps  = BC * NSTRIP * NSEG;      // 3072
    const int blocks = warps / (NTHREADS / 32); // 384
    opening_kernel<<<blocks, NTHREADS>>>(img, ker, out);
}

// round 15
// speedup vs baseline: 1.0950x; 1.0950x over previous
#include <cuda_runtime.h>
#include <cuda_bf16.h>

#define BIG 1e4f
#define IMH 1024
#define IMW 1024

constexpr int TY      = 32;               // output rows per warp
constexpr int NSEG    = 4;                // 1024/256: warp covers 256 floats
constexpr int NSTRIP  = IMH / TY;         // 32
constexpr int NTHREADS = 256;             // 8 warps / block
// warps = 24*32*4 = 3072 -> 384 blocks -> 20.8 warps/SM, ALL resident (3 blocks/SM)

// ---------------- cross fast path: 8 output columns per lane ----------------
// Distance-1 prefetch of the two main float4 loads; halo float2s are in-iteration
// (they hit L1: same lines as neighbor lanes' main loads).
// EDGE=false: strip interior in y (rows y0-2..y0+TY+1 all in-bounds) -> no clamps.
template<bool EDGE>
__device__ __forceinline__ void run_warp8_cross(const float* __restrict__ src,
                                                float*       __restrict__ dst,
                                                int x0, int y0)
{
    float eA[10], eB[10];  // erosion rows q-1, q   (x0-1 .. x0+8)
    float dA[8],  dB[8];   // dilation rows q-2, q-1 (x0 .. x0+7)
#pragma unroll
    for (int k = 0; k < 10; k++) { eA[k] = BIG; eB[k] = BIG; }
#pragma unroll
    for (int k = 0; k < 8; k++)  { dA[k] = -BIG; dB[k] = -BIG; }

    const bool xlo  = (x0 == 0);            // eroded pos x0-1 == -1
    const bool xhi  = (x0 == IMW - 8);      // eroded pos x0+8 == IMW
    const int  offL = xlo ? 0 : -2;
    const int  offR = (x0 <= IMW - 10) ? 8 : 0;
    const float* __restrict__ pbase = src + x0;
    const int qlast = y0 + TY + 1;

    // ---- prologue: load row y0-2 (clamped if EDGE) ----
    const float* pcur;
    {
        int q0 = y0 - 2;
        if (EDGE) { int qc = q0 < 0 ? 0 : q0; pcur = pbase + (size_t)qc * IMW; }
        else      { pcur = pbase + (size_t)q0 * IMW; }
    }
    float4 cv0 = *reinterpret_cast<const float4*>(pcur);
    float4 cv1 = *reinterpret_cast<const float4*>(pcur + 4);

#pragma unroll 3
    for (int q = y0 - 2; q <= qlast; q++) {
        // ---- prefetch next row's main loads (always in-bounds via min/clamp) ----
        int qn = q + 1 > qlast ? qlast : q + 1;
        const float* pnxt;
        if (EDGE) {
            int qc = qn < 0 ? 0 : (qn >= IMH ? IMH - 1 : qn);
            pnxt = pbase + (size_t)qc * IMW;
        } else {
            pnxt = pbase + (size_t)qn * IMW;
        }
        float4 nv0 = *reinterpret_cast<const float4*>(pnxt);
        float4 nv1 = *reinterpret_cast<const float4*>(pnxt + 4);

        // ---- current row halo loads (L1 hits) ----
        float2 lv = *reinterpret_cast<const float2*>(pcur + offL);
        float2 rv = *reinterpret_cast<const float2*>(pcur + offR);
        if (xlo) { lv.x = BIG; lv.y = BIG; }
        if (xhi) { rv.x = BIG; rv.y = BIG; }

        float w[12];
        w[0]=lv.x;  w[1]=lv.y;
        w[2]=cv0.x; w[3]=cv0.y; w[4]=cv0.z; w[5]=cv0.w;
        w[6]=cv1.x; w[7]=cv1.y; w[8]=cv1.z; w[9]=cv1.w;
        w[10]=rv.x; w[11]=rv.y;
        if (EDGE && (q < 0 || q >= IMH)) {
#pragma unroll
            for (int k = 0; k < 12; k++) w[k] = BIG;
        }

        // ---- erosion contributions of input row q (10-wide) ----
        float eC[10];
#pragma unroll
        for (int k = 0; k < 10; k++) {
            float h = fminf(fminf(w[k], w[k + 1]), w[k + 2]);
            eC[k] = w[k + 1];               // mask row 0: center only
            eB[k] = fminf(eB[k], h);        // mask row 1: full
            eA[k] = fminf(eA[k], w[k + 1]); // mask row 2: center only
        }

        // ---- eA complete: eroded row ry = q-1; -BIG padding ----
        if (EDGE) {
            int ry = q - 1;
            if (ry < 0 || ry >= IMH) {
#pragma unroll
                for (int k = 0; k < 10; k++) eA[k] = -BIG;
            } else {
                if (xlo) eA[0] = -BIG;
                if (xhi) eA[9] = -BIG;
            }
        } else {
            if (xlo) eA[0] = -BIG;
            if (xhi) eA[9] = -BIG;
        }

        // ---- dilation contributions of eroded row (8-wide) ----
        float dC[8];
#pragma unroll
        for (int k = 0; k < 8; k++) {
            float g = fmaxf(fmaxf(eA[k], eA[k + 1]), eA[k + 2]);
            dC[k] = eA[k + 1];
            dB[k] = fmaxf(dB[k], g);
            dA[k] = fmaxf(dA[k], eA[k + 1]);
        }

        // ---- dA complete: output row sy = q-2 ----
        if (q >= y0 + 2) {
            int sy = q - 2;
            float* o = dst + (size_t)sy * IMW + x0;
            *reinterpret_cast<float4*>(o)     = make_float4(dA[0], dA[1], dA[2], dA[3]);
            *reinterpret_cast<float4*>(o + 4) = make_float4(dA[4], dA[5], dA[6], dA[7]);
        }

        // ---- rotate pipelines (unroll 3 == period -> renamed away) ----
#pragma unroll
        for (int k = 0; k < 10; k++) { eA[k] = eB[k]; eB[k] = eC[k]; }
#pragma unroll
        for (int k = 0; k < 8; k++)  { dA[k] = dB[k]; dB[k] = dC[k]; }
        cv0 = nv0; cv1 = nv1; pcur = pnxt;
    }
}

// ---------------- generic-mask fallback: 4 columns per call ----------------
__device__ void run_warp4_generic(const float* __restrict__ src,
                                  float*       __restrict__ dst,
                                  const int* km, int x0, int y0)
{
    float eA[6], eB[6];
    float dA[4], dB[4];
#pragma unroll
    for (int k = 0; k < 6; k++) { eA[k] = BIG; eB[k] = BIG; }
#pragma unroll
    for (int k = 0; k < 4; k++) { dA[k] = -BIG; dB[k] = -BIG; }

    const bool xlo = (x0 == 0);
    const bool xhi = (x0 == IMW - 4);
    const int  offL = (x0 >= 2)       ? -2 : 0;
    const int  offR = (x0 <= IMW - 8) ?  4 : 0;
    const bool padL = (x0 < 2);
    const bool padR = (x0 > IMW - 8);
    const float* __restrict__ pbase = src + x0;

    for (int q = y0 - 2; q <= y0 + TY + 1; q++) {
        int qc = q < 0 ? 0 : (q >= IMH ? IMH - 1 : q);
        const float* p = pbase + (size_t)qc * IMW;
        float4 v  = *reinterpret_cast<const float4*>(p);
        float2 lv = *reinterpret_cast<const float2*>(p + offL);
        float2 rv = *reinterpret_cast<const float2*>(p + offR);
        if (padL) { lv.x = BIG; lv.y = BIG; }
        if (padR) { rv.x = BIG; rv.y = BIG; }
        float w[8];
        w[0]=lv.x; w[1]=lv.y; w[2]=v.x; w[3]=v.y; w[4]=v.z; w[5]=v.w; w[6]=rv.x; w[7]=rv.y;
        if (q < 0 || q >= IMH) {
#pragma unroll
            for (int k = 0; k < 8; k++) w[k] = BIG;
        }

        float c0[6], c1[6], c2[6];
#pragma unroll
        for (int k = 0; k < 6; k++) { c0[k] = BIG; c1[k] = BIG; c2[k] = BIG; }
#pragma unroll
        for (int j = 0; j < 3; j++) {
            if (km[0*3 + j]) {
#pragma unroll
                for (int k = 0; k < 6; k++) c0[k] = fminf(c0[k], w[k + j]);
            }
            if (km[1*3 + j]) {
#pragma unroll
                for (int k = 0; k < 6; k++) c1[k] = fminf(c1[k], w[k + j]);
            }
            if (km[2*3 + j]) {
#pragma unroll
                for (int k = 0; k < 6; k++) c2[k] = fminf(c2[k], w[k + j]);
            }
        }
        float eC[6];
#pragma unroll
        for (int k = 0; k < 6; k++) {
            eC[k] = c0[k];
            eB[k] = fminf(eB[k], c1[k]);
            eA[k] = fminf(eA[k], c2[k]);
        }

        int ry = q - 1;
        if (ry < 0 || ry >= IMH) {
#pragma unroll
            for (int k = 0; k < 6; k++) eA[k] = -BIG;
        } else {
            if (xlo) eA[0] = -BIG;
            if (xhi) eA[5] = -BIG;
        }

        float g0[4], g1[4], g2[4];
#pragma unroll
        for (int k = 0; k < 4; k++) { g0[k] = -BIG; g1[k] = -BIG; g2[k] = -BIG; }
#pragma unroll
        for (int j = 0; j < 3; j++) {
            if (km[0*3 + j]) {
#pragma unroll
                for (int k = 0; k < 4; k++) g0[k] = fmaxf(g0[k], eA[k + j]);
            }
            if (km[1*3 + j]) {
#pragma unroll
                for (int k = 0; k < 4; k++) g1[k] = fmaxf(g1[k], eA[k + j]);
            }
            if (km[2*3 + j]) {
#pragma unroll
                for (int k = 0; k < 4; k++) g2[k] = fmaxf(g2[k], eA[k + j]);
            }
        }
        float dC[4];
#pragma unroll
        for (int k = 0; k < 4; k++) {
            dC[k] = g0[k];
            dB[k] = fmaxf(dB[k], g1[k]);
            dA[k] = fmaxf(dA[k], g2[k]);
        }

        if (q >= y0 + 2) {
            int sy = q - 2;
            *reinterpret_cast<float4*>(dst + (size_t)sy * IMW + x0) =
                make_float4(dA[0], dA[1], dA[2], dA[3]);
        }

#pragma unroll
        for (int k = 0; k < 6; k++) { eA[k] = eB[k]; eB[k] = eC[k]; }
#pragma unroll
        for (int k = 0; k < 4; k++) { dA[k] = dB[k]; dB[k] = dC[k]; }
    }
}

__global__ __launch_bounds__(NTHREADS, 3)
void opening_kernel(const float* __restrict__ img,
                    const int*   __restrict__ ker,
                    float*       __restrict__ out)
{
    int km[9];
#pragma unroll
    for (int i = 0; i < 9; i++) km[i] = ker[i];
    const bool cross = (km[0] == 0) && (km[1] == 1) && (km[2] == 0) &&
                       (km[3] == 1) && (km[4] == 1) && (km[5] == 1) &&
                       (km[6] == 0) && (km[7] == 1) && (km[8] == 0);

    const int gw   = blockIdx.x * (NTHREADS / 32) + (threadIdx.x >> 5);
    const int lane = threadIdx.x & 31;
    const int xseg   = gw & (NSEG - 1);       // 2 bits
    const int t      = gw >> 2;
    const int ystrip = t & (NSTRIP - 1);      // 5 bits
    const int bc     = t >> 5;

    const int x0 = xseg * 256 + lane * 8;
    const int y0 = ystrip * TY;

    const float* src = img + (size_t)bc * (IMH * IMW);
    float*       dst = out + (size_t)bc * (IMH * IMW);

    if (cross) {
        if (y0 >= 2 && y0 + TY + 2 < IMH)     // rows y0-2 .. y0+TY+2 (incl. prefetch) in-bounds
            run_warp8_cross<false>(src, dst, x0, y0);
        else
            run_warp8_cross<true >(src, dst, x0, y0);
    } else {
        run_warp4_generic(src, dst, km, x0,     y0);
        run_warp4_generic(src, dst, km, x0 + 4, y0);
    }
}

extern "C" void kernel_launch(void* const* d_in, const int* in_sizes, int n_in,
                              void* d_out, int out_size)
{
    const float* img = (const float*)d_in[0];   // [8,3,1024,1024] fp32
    const int*   ker = (const int*)d_in[1];     // [3,3] int32 mask
    float*       out = (float*)d_out;

    const int BC = in_sizes[0] / (IMH * IMW);   // 24
    const int warps  = BC * NSTRIP * NSEG;      // 3072
    const int blocks = warps / (NTHREADS / 32); // 384
    opening_kernel<<<blocks, NTHREADS>>>(img, ker, out);
}

// round 16
// speedup vs baseline: 1.2423x; 1.1345x over previous
#include <cuda_runtime.h>
#include <cuda_bf16.h>
#include <cstdint>

#define BIG 1e4f
#define IMH 1024
#define IMW 1024

constexpr int TYB      = 64;              // output rows per block
constexpr int NTHREADS = 256;             // 8 warps; block covers full 1024-wide row
constexpr int NSTRIP   = IMH / TYB;       // 16
constexpr int S        = 8;               // ring stages
constexpr int D        = 4;               // prefetch distance (rows)
constexpr int PADF     = 16;              // front pad floats (16B-aligned data start)
constexpr int STW      = PADF + IMW + 16; // stage width in floats (1056)

__device__ __forceinline__ void cp_async16(uint32_t dst_smem, const float* src) {
    asm volatile("cp.async.cg.shared.global [%0], [%1], 16;\n"
                 :: "r"(dst_smem), "l"(src) : "memory");
}
__device__ __forceinline__ void cp_commit() {
    asm volatile("cp.async.commit_group;\n" ::: "memory");
}
template<int N>
__device__ __forceinline__ void cp_wait() {
    asm volatile("cp.async.wait_group %0;\n" :: "n"(N) : "memory");
}

// ---------------- generic-mask fallback (direct LDG, any kernel) ----------------
__device__ void run_generic4(const float* __restrict__ src,
                             float*       __restrict__ dst,
                             const int* km, int x0, int y0, int rows)
{
    float eA[6], eB[6], dA[4], dB[4];
#pragma unroll
    for (int k = 0; k < 6; k++) { eA[k] = BIG; eB[k] = BIG; }
#pragma unroll
    for (int k = 0; k < 4; k++) { dA[k] = -BIG; dB[k] = -BIG; }

    const bool xlo = (x0 == 0);
    const bool xhi = (x0 == IMW - 4);
    const int  offL = (x0 >= 2)       ? -2 : 0;
    const int  offR = (x0 <= IMW - 8) ?  4 : 0;
    const bool padL = (x0 < 2);
    const bool padR = (x0 > IMW - 8);
    const float* __restrict__ pbase = src + x0;

    for (int q = y0 - 2; q <= y0 + rows + 1; q++) {
        int qc = q < 0 ? 0 : (q >= IMH ? IMH - 1 : q);
        const float* p = pbase + (size_t)qc * IMW;
        float4 v  = *reinterpret_cast<const float4*>(p);
        float2 lv = *reinterpret_cast<const float2*>(p + offL);
        float2 rv = *reinterpret_cast<const float2*>(p + offR);
        if (padL) { lv.x = BIG; lv.y = BIG; }
        if (padR) { rv.x = BIG; rv.y = BIG; }
        float w[8];
        w[0]=lv.x; w[1]=lv.y; w[2]=v.x; w[3]=v.y; w[4]=v.z; w[5]=v.w; w[6]=rv.x; w[7]=rv.y;
        if (q < 0 || q >= IMH) {
#pragma unroll
            for (int k = 0; k < 8; k++) w[k] = BIG;
        }

        float c0[6], c1[6], c2[6];
#pragma unroll
        for (int k = 0; k < 6; k++) { c0[k] = BIG; c1[k] = BIG; c2[k] = BIG; }
#pragma unroll
        for (int j = 0; j < 3; j++) {
            if (km[0*3 + j]) {
#pragma unroll
                for (int k = 0; k < 6; k++) c0[k] = fminf(c0[k], w[k + j]);
            }
            if (km[1*3 + j]) {
#pragma unroll
                for (int k = 0; k < 6; k++) c1[k] = fminf(c1[k], w[k + j]);
            }
            if (km[2*3 + j]) {
#pragma unroll
                for (int k = 0; k < 6; k++) c2[k] = fminf(c2[k], w[k + j]);
            }
        }
        float eC[6];
#pragma unroll
        for (int k = 0; k < 6; k++) {
            eC[k] = c0[k]; eB[k] = fminf(eB[k], c1[k]); eA[k] = fminf(eA[k], c2[k]);
        }

        int ry = q - 1;
        if (ry < 0 || ry >= IMH) {
#pragma unroll
            for (int k = 0; k < 6; k++) eA[k] = -BIG;
        } else {
            if (xlo) eA[0] = -BIG;
            if (xhi) eA[5] = -BIG;
        }

        float g0[4], g1[4], g2[4];
#pragma unroll
        for (int k = 0; k < 4; k++) { g0[k] = -BIG; g1[k] = -BIG; g2[k] = -BIG; }
#pragma unroll
        for (int j = 0; j < 3; j++) {
            if (km[0*3 + j]) {
#pragma unroll
                for (int k = 0; k < 4; k++) g0[k] = fmaxf(g0[k], eA[k + j]);
            }
            if (km[1*3 + j]) {
#pragma unroll
                for (int k = 0; k < 4; k++) g1[k] = fmaxf(g1[k], eA[k + j]);
            }
            if (km[2*3 + j]) {
#pragma unroll
                for (int k = 0; k < 4; k++) g2[k] = fmaxf(g2[k], eA[k + j]);
            }
        }
        float dC[4];
#pragma unroll
        for (int k = 0; k < 4; k++) {
            dC[k] = g0[k]; dB[k] = fmaxf(dB[k], g1[k]); dA[k] = fmaxf(dA[k], g2[k]);
        }

        if (q >= y0 + 2) {
            int sy = q - 2;
            *reinterpret_cast<float4*>(dst + (size_t)sy * IMW + x0) =
                make_float4(dA[0], dA[1], dA[2], dA[3]);
        }

#pragma unroll
        for (int k = 0; k < 6; k++) { eA[k] = eB[k]; eB[k] = eC[k]; }
#pragma unroll
        for (int k = 0; k < 4; k++) { dA[k] = dB[k]; dB[k] = dC[k]; }
    }
}

__global__ __launch_bounds__(NTHREADS, 3)
void opening_kernel(const float* __restrict__ img,
                    const int*   __restrict__ ker,
                    float*       __restrict__ out)
{
    __shared__ float ring[S][STW];

    int km[9];
#pragma unroll
    for (int i = 0; i < 9; i++) km[i] = ker[i];
    const bool cross = (km[0] == 0) && (km[1] == 1) && (km[2] == 0) &&
                       (km[3] == 1) && (km[4] == 1) && (km[5] == 1) &&
                       (km[6] == 0) && (km[7] == 1) && (km[8] == 0);

    const int tid  = threadIdx.x;
    const int wid  = tid >> 5;
    const int lane = tid & 31;
    const int strip = blockIdx.x & (NSTRIP - 1);   // 16 strips
    const int bc    = blockIdx.x >> 4;             // batch*channel
    const int y0    = strip * TYB;

    const float* __restrict__ src = img + (size_t)bc * (IMH * IMW);
    float*       __restrict__ dst = out + (size_t)bc * (IMH * IMW);

    if (!cross) {
        const int x0 = wid * 128 + lane * 4;
        run_generic4(src, dst, km, x0, y0, TYB);
        return;
    }

    // ---- sentinels: x=-2,-1 and x=1024,1025 are +BIG forever ----
    if (tid < S) {
        ring[tid][PADF - 2]      = BIG;
        ring[tid][PADF - 1]      = BIG;
        ring[tid][PADF + IMW]    = BIG;
        ring[tid][PADF + IMW + 1]= BIG;
    }

    // per-thread copy slot: 16B chunk (tid*4 floats) of each row
    uint32_t rbase = (uint32_t)__cvta_generic_to_shared(&ring[0][0]);
    const uint32_t dst_off = (uint32_t)((PADF + tid * 4) * 4);
    const float* srcrow = src + tid * 4;

    // ---- prologue: prefetch rows i=0..D-1  (row q = y0-2+i, clamped) ----
#pragma unroll
    for (int i = 0; i < D; i++) {
        int r  = y0 - 2 + i;
        int rc = r < 0 ? 0 : (r >= IMH ? IMH - 1 : r);
        cp_async16(rbase + (uint32_t)(i * STW * 4) + dst_off, srcrow + (size_t)rc * IMW);
        cp_commit();
    }

    // ---- per-lane state ----
    const int x0  = wid * 128 + lane * 4;
    const bool xlo = (x0 == 0);
    const bool xhi = (x0 == IMW - 4);
    float eA[6], eB[6], dA[4], dB[4];
#pragma unroll
    for (int k = 0; k < 6; k++) { eA[k] = BIG; eB[k] = BIG; }
#pragma unroll
    for (int k = 0; k < 4; k++) { dA[k] = -BIG; dB[k] = -BIG; }

#pragma unroll 4
    for (int i = 0; i < TYB + 4; i++) {           // q = y0-2+i
        const int q = y0 - 2 + i;

        // prefetch row i+D into stage (i+D)%S
        {
            int r  = q + D;
            int rc = r < 0 ? 0 : (r >= IMH ? IMH - 1 : r);
            cp_async16(rbase + (uint32_t)(((i + D) & (S - 1)) * STW * 4) + dst_off,
                       srcrow + (size_t)rc * IMW);
            cp_commit();
        }
        cp_wait<D>();
        __syncthreads();

        // ---- consume row q from stage i%S: 8-wide window x0-2..x0+5 ----
        const float* st = &ring[i & (S - 1)][0];
        float4 c  = *reinterpret_cast<const float4*>(st + PADF + x0);
        float2 lv = *reinterpret_cast<const float2*>(st + PADF + x0 - 2);
        float2 rv = *reinterpret_cast<const float2*>(st + PADF + x0 + 4);
        float w[8];
        w[0]=lv.x; w[1]=lv.y; w[2]=c.x; w[3]=c.y; w[4]=c.z; w[5]=c.w; w[6]=rv.x; w[7]=rv.y;
        if (q < 0 || q >= IMH) {                  // uniform per block
#pragma unroll
            for (int k = 0; k < 8; k++) w[k] = BIG;
        }

        // ---- erosion contributions of row q (6-wide: x0-1..x0+4) ----
        float eC[6];
#pragma unroll
        for (int k = 0; k < 6; k++) {
            float h = fminf(fminf(w[k], w[k + 1]), w[k + 2]);
            eC[k] = w[k + 1];
            eB[k] = fminf(eB[k], h);
            eA[k] = fminf(eA[k], w[k + 1]);
        }

        // ---- eA complete: eroded row ry = q-1; -BIG padding ----
        {
            int ry = q - 1;
            if (ry < 0 || ry >= IMH) {            // uniform
#pragma unroll
                for (int k = 0; k < 6; k++) eA[k] = -BIG;
            } else {
                if (xlo) eA[0] = -BIG;
                if (xhi) eA[5] = -BIG;
            }
        }

        // ---- dilation of eroded row (4-wide) ----
        float dC[4];
#pragma unroll
        for (int k = 0; k < 4; k++) {
            float g = fmaxf(fmaxf(eA[k], eA[k + 1]), eA[k + 2]);
            dC[k] = eA[k + 1];
            dB[k] = fmaxf(dB[k], g);
            dA[k] = fmaxf(dA[k], eA[k + 1]);
        }

        // ---- dA complete: output row sy = q-2 ----
        if (q >= y0 + 2) {
            int sy = q - 2;
            *reinterpret_cast<float4*>(dst + (size_t)sy * IMW + x0) =
                make_float4(dA[0], dA[1], dA[2], dA[3]);
        }

        // ---- rotate ----
#pragma unroll
        for (int k = 0; k < 6; k++) { eA[k] = eB[k]; eB[k] = eC[k]; }
#pragma unroll
        for (int k = 0; k < 4; k++) { dA[k] = dB[k]; dB[k] = dC[k]; }
    }
}

extern "C" void kernel_launch(void* const* d_in, const int* in_sizes, int n_in,
                              void* d_out, int out_size)
{
    const float* img = (const float*)d_in[0];   // [8,3,1024,1024] fp32
    const int*   ker = (const int*)d_in[1];     // [3,3] int32 mask
    float*       out = (float*)d_out;

    const int BC = in_sizes[0] / (IMH * IMW);   // 24
    const int blocks = BC * NSTRIP;             // 384
    opening_kernel<<<blocks, NTHREADS>>>(img, ker, out);
}

// round 17
// speedup vs baseline: 1.2731x; 1.0248x over previous
#include <cuda_runtime.h>
#include <cuda_bf16.h>
#include <cstdint>

#define BIG 1e4f
#define IMH 1024
#define IMW 1024

constexpr int TYB      = 64;              // output rows per block
constexpr int NTHREADS = 256;             // 8 warps; block covers full 1024-wide row
constexpr int NSTRIP   = IMH / TYB;       // 16
constexpr int SP       = 4;               // ring stages (pairs of rows)
constexpr int DP       = 2;               // prefetch distance in pairs (= 4 rows)
constexpr int PADF     = 16;              // front pad floats (16B-aligned data start)
constexpr int STW      = PADF + IMW + 16; // row width in floats (1056)

__device__ __forceinline__ void cp_async16(uint32_t dst_smem, const float* src) {
    asm volatile("cp.async.cg.shared.global [%0], [%1], 16;\n"
                 :: "r"(dst_smem), "l"(src) : "memory");
}
__device__ __forceinline__ void cp_commit() {
    asm volatile("cp.async.commit_group;\n" ::: "memory");
}
template<int N>
__device__ __forceinline__ void cp_wait() {
    asm volatile("cp.async.wait_group %0;\n" :: "n"(N) : "memory");
}

struct LaneState {
    float eA[6], eB[6], dA[4], dB[4];
};

// one pipeline step for input row q (window read from smem stage row st)
__device__ __forceinline__ void process_row(const float* __restrict__ st, int q,
                                            int x0, bool xlo, bool xhi, int y0,
                                            float* __restrict__ dst, LaneState& s)
{
    float4 c  = *reinterpret_cast<const float4*>(st + PADF + x0);
    float2 lv = *reinterpret_cast<const float2*>(st + PADF + x0 - 2);
    float2 rv = *reinterpret_cast<const float2*>(st + PADF + x0 + 4);
    float w[8];
    w[0]=lv.x; w[1]=lv.y; w[2]=c.x; w[3]=c.y; w[4]=c.z; w[5]=c.w; w[6]=rv.x; w[7]=rv.y;
    if (q < 0 || q >= IMH) {                  // uniform per block
#pragma unroll
        for (int k = 0; k < 8; k++) w[k] = BIG;
    }

    // erosion contributions of row q (6-wide: x0-1..x0+4)
    float eC[6];
#pragma unroll
    for (int k = 0; k < 6; k++) {
        float h = fminf(fminf(w[k], w[k + 1]), w[k + 2]);
        eC[k] = w[k + 1];                 // mask row 0: center only
        s.eB[k] = fminf(s.eB[k], h);      // mask row 1: full
        s.eA[k] = fminf(s.eA[k], w[k + 1]); // mask row 2: center only
    }

    // eA complete: eroded row ry = q-1; -BIG padding
    {
        int ry = q - 1;
        if (ry < 0 || ry >= IMH) {        // uniform
#pragma unroll
            for (int k = 0; k < 6; k++) s.eA[k] = -BIG;
        } else {
            if (xlo) s.eA[0] = -BIG;
            if (xhi) s.eA[5] = -BIG;
        }
    }

    // dilation of eroded row (4-wide)
    float dC[4];
#pragma unroll
    for (int k = 0; k < 4; k++) {
        float g = fmaxf(fmaxf(s.eA[k], s.eA[k + 1]), s.eA[k + 2]);
        dC[k] = s.eA[k + 1];
        s.dB[k] = fmaxf(s.dB[k], g);
        s.dA[k] = fmaxf(s.dA[k], s.eA[k + 1]);
    }

    // dA complete: output row sy = q-2
    if (q >= y0 + 2) {
        int sy = q - 2;
        *reinterpret_cast<float4*>(dst + (size_t)sy * IMW + x0) =
            make_float4(s.dA[0], s.dA[1], s.dA[2], s.dA[3]);
    }

    // rotate
#pragma unroll
    for (int k = 0; k < 6; k++) { s.eA[k] = s.eB[k]; s.eB[k] = eC[k]; }
#pragma unroll
    for (int k = 0; k < 4; k++) { s.dA[k] = s.dB[k]; s.dB[k] = dC[k]; }
}

// ---------------- generic-mask fallback (direct LDG, any kernel) ----------------
__device__ void run_generic4(const float* __restrict__ src,
                             float*       __restrict__ dst,
                             const int* km, int x0, int y0, int rows)
{
    float eA[6], eB[6], dA[4], dB[4];
#pragma unroll
    for (int k = 0; k < 6; k++) { eA[k] = BIG; eB[k] = BIG; }
#pragma unroll
    for (int k = 0; k < 4; k++) { dA[k] = -BIG; dB[k] = -BIG; }

    const bool xlo = (x0 == 0);
    const bool xhi = (x0 == IMW - 4);
    const int  offL = (x0 >= 2)       ? -2 : 0;
    const int  offR = (x0 <= IMW - 8) ?  4 : 0;
    const bool padL = (x0 < 2);
    const bool padR = (x0 > IMW - 8);
    const float* __restrict__ pbase = src + x0;

    for (int q = y0 - 2; q <= y0 + rows + 1; q++) {
        int qc = q < 0 ? 0 : (q >= IMH ? IMH - 1 : q);
        const float* p = pbase + (size_t)qc * IMW;
        float4 v  = *reinterpret_cast<const float4*>(p);
        float2 lv = *reinterpret_cast<const float2*>(p + offL);
        float2 rv = *reinterpret_cast<const float2*>(p + offR);
        if (padL) { lv.x = BIG; lv.y = BIG; }
        if (padR) { rv.x = BIG; rv.y = BIG; }
        float w[8];
        w[0]=lv.x; w[1]=lv.y; w[2]=v.x; w[3]=v.y; w[4]=v.z; w[5]=v.w; w[6]=rv.x; w[7]=rv.y;
        if (q < 0 || q >= IMH) {
#pragma unroll
            for (int k = 0; k < 8; k++) w[k] = BIG;
        }

        float c0[6], c1[6], c2[6];
#pragma unroll
        for (int k = 0; k < 6; k++) { c0[k] = BIG; c1[k] = BIG; c2[k] = BIG; }
#pragma unroll
        for (int j = 0; j < 3; j++) {
            if (km[0*3 + j]) {
#pragma unroll
                for (int k = 0; k < 6; k++) c0[k] = fminf(c0[k], w[k + j]);
            }
            if (km[1*3 + j]) {
#pragma unroll
                for (int k = 0; k < 6; k++) c1[k] = fminf(c1[k], w[k + j]);
            }
            if (km[2*3 + j]) {
#pragma unroll
                for (int k = 0; k < 6; k++) c2[k] = fminf(c2[k], w[k + j]);
            }
        }
        float eC[6];
#pragma unroll
        for (int k = 0; k < 6; k++) {
            eC[k] = c0[k]; eB[k] = fminf(eB[k], c1[k]); eA[k] = fminf(eA[k], c2[k]);
        }

        int ry = q - 1;
        if (ry < 0 || ry >= IMH) {
#pragma unroll
            for (int k = 0; k < 6; k++) eA[k] = -BIG;
        } else {
            if (xlo) eA[0] = -BIG;
            if (xhi) eA[5] = -BIG;
        }

        float g0[4], g1[4], g2[4];
#pragma unroll
        for (int k = 0; k < 4; k++) { g0[k] = -BIG; g1[k] = -BIG; g2[k] = -BIG; }
#pragma unroll
        for (int j = 0; j < 3; j++) {
            if (km[0*3 + j]) {
#pragma unroll
                for (int k = 0; k < 4; k++) g0[k] = fmaxf(g0[k], eA[k + j]);
            }
            if (km[1*3 + j]) {
#pragma unroll
                for (int k = 0; k < 4; k++) g1[k] = fmaxf(g1[k], eA[k + j]);
            }
            if (km[2*3 + j]) {
#pragma unroll
                for (int k = 0; k < 4; k++) g2[k] = fmaxf(g2[k], eA[k + j]);
            }
        }
        float dC[4];
#pragma unroll
        for (int k = 0; k < 4; k++) {
            dC[k] = g0[k]; dB[k] = fmaxf(dB[k], g1[k]); dA[k] = fmaxf(dA[k], g2[k]);
        }

        if (q >= y0 + 2) {
            int sy = q - 2;
            *reinterpret_cast<float4*>(dst + (size_t)sy * IMW + x0) =
                make_float4(dA[0], dA[1], dA[2], dA[3]);
        }

#pragma unroll
        for (int k = 0; k < 6; k++) { eA[k] = eB[k]; eB[k] = eC[k]; }
#pragma unroll
        for (int k = 0; k < 4; k++) { dA[k] = dB[k]; dB[k] = dC[k]; }
    }
}

__global__ __launch_bounds__(NTHREADS, 3)
void opening_kernel(const float* __restrict__ img,
                    const int*   __restrict__ ker,
                    float*       __restrict__ out)
{
    __shared__ float ring[SP][2][STW];   // 4 stages x 2 rows

    int km[9];
#pragma unroll
    for (int i = 0; i < 9; i++) km[i] = ker[i];
    const bool cross = (km[0] == 0) && (km[1] == 1) && (km[2] == 0) &&
                       (km[3] == 1) && (km[4] == 1) && (km[5] == 1) &&
                       (km[6] == 0) && (km[7] == 1) && (km[8] == 0);

    const int tid  = threadIdx.x;
    const int wid  = tid >> 5;
    const int lane = tid & 31;
    const int strip = blockIdx.x & (NSTRIP - 1);   // 16 strips
    const int bc    = blockIdx.x >> 4;             // batch*channel
    const int y0    = strip * TYB;

    const float* __restrict__ src = img + (size_t)bc * (IMH * IMW);
    float*       __restrict__ dst = out + (size_t)bc * (IMH * IMW);

    if (!cross) {
        const int x0 = wid * 128 + lane * 4;
        run_generic4(src, dst, km, x0, y0, TYB);
        return;
    }

    // ---- sentinels: x=-2,-1 and x=1024,1025 are +BIG forever ----
    if (tid < SP * 2) {
        float* row = &ring[tid >> 1][tid & 1][0];
        row[PADF - 2]       = BIG;
        row[PADF - 1]       = BIG;
        row[PADF + IMW]     = BIG;
        row[PADF + IMW + 1] = BIG;
    }

    uint32_t rbase = (uint32_t)__cvta_generic_to_shared(&ring[0][0][0]);
    const uint32_t dst_off = (uint32_t)((PADF + tid * 4) * 4);
    const uint32_t stage_bytes = (uint32_t)(2 * STW * 4);
    const uint32_t row_bytes   = (uint32_t)(STW * 4);
    const float* srcrow = src + tid * 4;

    // ---- prologue: prefetch pairs 0..DP-1 (rows q = y0-2+2p, +1; clamped) ----
#pragma unroll
    for (int p = 0; p < DP; p++) {
        int r0 = y0 - 2 + 2 * p;
        int r1 = r0 + 1;
        int r0c = r0 < 0 ? 0 : (r0 >= IMH ? IMH - 1 : r0);
        int r1c = r1 < 0 ? 0 : (r1 >= IMH ? IMH - 1 : r1);
        uint32_t sb = rbase + (uint32_t)p * stage_bytes + dst_off;
        cp_async16(sb,             srcrow + (size_t)r0c * IMW);
        cp_async16(sb + row_bytes, srcrow + (size_t)r1c * IMW);
        cp_commit();
    }

    // ---- per-lane state ----
    const int x0  = wid * 128 + lane * 4;
    const bool xlo = (x0 == 0);
    const bool xhi = (x0 == IMW - 4);
    LaneState s;
#pragma unroll
    for (int k = 0; k < 6; k++) { s.eA[k] = BIG; s.eB[k] = BIG; }
#pragma unroll
    for (int k = 0; k < 4; k++) { s.dA[k] = -BIG; s.dB[k] = -BIG; }

    constexpr int NPAIR = (TYB + 4) / 2;          // 34 pairs = 68 rows
#pragma unroll 2
    for (int p = 0; p < NPAIR; p++) {
        const int q0 = y0 - 2 + 2 * p;

        // prefetch pair p+DP into stage (p+DP)%SP
        {
            int r0 = q0 + 2 * DP;
            int r1 = r0 + 1;
            int r0c = r0 < 0 ? 0 : (r0 >= IMH ? IMH - 1 : r0);
            int r1c = r1 < 0 ? 0 : (r1 >= IMH ? IMH - 1 : r1);
            uint32_t sb = rbase + (uint32_t)(((p + DP) & (SP - 1)) * stage_bytes) + dst_off;
            cp_async16(sb,             srcrow + (size_t)r0c * IMW);
            cp_async16(sb + row_bytes, srcrow + (size_t)r1c * IMW);
            cp_commit();
        }
        cp_wait<DP>();
        __syncthreads();

        // ---- consume pair p: rows q0, q0+1 ----
        const float* st0 = &ring[p & (SP - 1)][0][0];
        const float* st1 = &ring[p & (SP - 1)][1][0];
        process_row(st0, q0,     x0, xlo, xhi, y0, dst, s);
        process_row(st1, q0 + 1, x0, xlo, xhi, y0, dst, s);
    }
}

extern "C" void kernel_launch(void* const* d_in, const int* in_sizes, int n_in,
                              void* d_out, int out_size)
{
    const float* img = (const float*)d_in[0];   // [8,3,1024,1024] fp32
    const int*   ker = (const int*)d_in[1];     // [3,3] int32 mask
    float*       out = (float*)d_out;

    const int BC = in_sizes[0] / (IMH * IMW);   // 24
    const int blocks = BC * NSTRIP;             // 384
    opening_kernel<<<blocks, NTHREADS>>>(img, ker, out);
}